// round 4
// baseline (speedup 1.0000x reference)
#include <cuda_runtime.h>
#include <cstdint>

// Problem constants (fixed shapes per reference)
#define B_   2
#define N_   16384
#define S_   4096        // npoint
#define C_   64
#define NS_  32          // nsample
#define NCID (B_*S_)     // 8192 centroids total

// Scratch (static __device__ arrays: allocation-free per harness rules)
__device__ float g_F1[(size_t)B_ * N_ * 64];   // feats@W1[3:] + b1, [b][n][64]  (8MB)
__device__ int   g_idx[NCID * NS_];            // ball query result               (1MB)

// ---------------------------------------------------------------------------
// Kernel 1: F1[b][n][j] = sum_c feats[b][c][n] * W1[3+c][j] + b1[j]
// grid (N/64, B), 256 threads
// ---------------------------------------------------------------------------
__global__ void k_f1(const float* __restrict__ feats,
                     const float* __restrict__ W1,
                     const float* __restrict__ b1) {
    __shared__ float sF[64 * 64];   // [c][n_local]
    __shared__ float sW[64 * 64];   // [c][j]
    __shared__ float sb[64];
    int b  = blockIdx.y;
    int n0 = blockIdx.x * 64;
    int tid = threadIdx.x;

    for (int i = tid; i < 4096; i += 256) sW[i] = W1[192 + i];  // rows 3..66
    if (tid < 64) sb[tid] = b1[tid];
    const float* fb = feats + (size_t)b * 64 * N_;
    for (int i = tid; i < 4096; i += 256) {
        int c = i >> 6, nn = i & 63;
        sF[c * 64 + nn] = fb[(size_t)c * N_ + n0 + nn];
    }
    __syncthreads();

    int n  = tid & 63;
    int j0 = (tid >> 6) * 16;
    float acc[16];
#pragma unroll
    for (int j = 0; j < 16; j++) acc[j] = sb[j0 + j];
#pragma unroll 8
    for (int c = 0; c < 64; c++) {
        float f = sF[c * 64 + n];
#pragma unroll
        for (int j = 0; j < 16; j++) acc[j] += f * sW[c * 64 + j0 + j];
    }
    float* dst = g_F1 + ((size_t)b * N_ + n0 + n) * 64 + j0;
#pragma unroll
    for (int j = 0; j < 16; j += 4) {
        float4 v = make_float4(acc[j], acc[j+1], acc[j+2], acc[j+3]);
        *(float4*)(dst + j) = v;
    }
}

// ---------------------------------------------------------------------------
// Kernel 2: ball query. One warp per centroid, 8 warps/block, smem point tiles.
// Replicates reference: first 32 indices (ascending) with d2 < r^2, using
// d2 = |c|^2 + |p|^2 - 2 c.p ; empty slots filled with first hit (0 if none).
// ---------------------------------------------------------------------------
__global__ void k_bq(const float* __restrict__ xyz) {
    const int TILE = 2048;
    __shared__ float spx[TILE], spy[TILE], spz[TILE], sn2[TILE];
    __shared__ int s_done;
    int tid  = threadIdx.x;
    int lane = tid & 31, w = tid >> 5;
    int cid  = blockIdx.x * 8 + w;
    int b = cid >> 12, s = cid & (S_ - 1);
    if (tid == 0) s_done = 0;

    const float* xb = xyz + (size_t)b * N_ * 3;
    float cx = xb[s*3], cy = xb[s*3+1], cz = xb[s*3+2];
    float cn2 = cx*cx + cy*cy + cz*cz;
    const float R2 = 0.4f * 0.4f;

    int  cnt = 0, firstn = 0;
    bool flagged = false;
    int* myidx = g_idx + cid * NS_;

    for (int t0 = 0; t0 < N_; t0 += TILE) {
        for (int i = tid; i < TILE; i += 256) {
            float x = xb[(t0+i)*3], y = xb[(t0+i)*3+1], z = xb[(t0+i)*3+2];
            spx[i] = x; spy[i] = y; spz[i] = z; sn2[i] = x*x + y*y + z*z;
        }
        __syncthreads();
        if (cnt < NS_) {
            for (int it = 0; it < TILE/32; it++) {
                int j = it*32 + lane;
                float d2 = cn2 + sn2[j] - 2.0f*(cx*spx[j] + cy*spy[j] + cz*spz[j]);
                bool hit = d2 < R2;
                unsigned mask = __ballot_sync(0xffffffffu, hit);
                if (mask) {
                    if (cnt == 0) firstn = t0 + it*32 + (__ffs(mask) - 1);
                    int pos = cnt + __popc(mask & ((1u << lane) - 1u));
                    if (hit && pos < NS_) myidx[pos] = t0 + j;
                    cnt += __popc(mask);
                    if (cnt >= NS_) break;
                }
            }
            if (cnt >= NS_ && !flagged) {
                flagged = true;
                if (lane == 0) atomicAdd(&s_done, 1);
            }
        }
        __syncthreads();
        if (s_done == 8) break;
    }
    if (cnt < NS_) {
        int fv = (cnt > 0) ? firstn : 0;
        if (lane < NS_ - cnt) myidx[cnt + lane] = fv;
    }
}

// ---------------------------------------------------------------------------
// Kernel 3: fused MLP + max-pool. 128 threads, 8 centroids per block.
// h1 = relu(F1[idx] + dxyz@W1[0:3])            -> smem h1T [64k][32n]
// h2 = relu(h1@W2+b2)                           -> smem h2T [64k][32n]
// h3 = relu(h2@W3+b3); out[c] = max_n h3[n][c]  -> global [b][c][s]
// ---------------------------------------------------------------------------
__global__ __launch_bounds__(128, 3)
void k_mlp(const float* __restrict__ xyz,
           const float* __restrict__ W1, const float* __restrict__ W2,
           const float* __restrict__ b2, const float* __restrict__ W3,
           const float* __restrict__ b3, float* __restrict__ outf) {
    extern __shared__ float sm[];
    float* sW2  = sm;            // 64*64
    float* sW3  = sm + 4096;     // 64*128
    float* sW1x = sW3 + 8192;    // 3*64
    float* sb2  = sW1x + 192;    // 64
    float* sb3  = sb2 + 64;      // 128
    float* h1T  = sb3 + 128;     // 64*32  [k][n]
    float* h2T  = h1T + 2048;    // 64*32  [k][n]
    int tid = threadIdx.x;

    for (int i = tid; i < 4096; i += 128) sW2[i] = W2[i];
    for (int i = tid; i < 8192; i += 128) sW3[i] = W3[i];
    if (tid < 64) { sW1x[tid] = W1[tid]; sW1x[64+tid] = W1[64+tid]; sW1x[128+tid] = W1[128+tid]; }
    if (tid < 64) sb2[tid] = b2[tid];
    sb3[tid] = b3[tid];
    __syncthreads();

    int tr = tid & 7;      int n0 = tr * 4;
    int tcg = tid >> 3;    int c2 = tcg * 4;   int c3 = tcg * 8;

    for (int ci = 0; ci < 8; ci++) {
        int cid = blockIdx.x * 8 + ci;
        int b = cid >> 12, s = cid & (S_ - 1);

        // ---- layer 1 (gather precomputed F1 + xyz part) ----
        {
            int n  = tid & 31;
            int j0 = (tid >> 5) * 16;
            int pidx = g_idx[cid * NS_ + n];
            const float* xb = xyz + (size_t)b * N_ * 3;
            float dx = xb[pidx*3+0] - xb[s*3+0];
            float dy = xb[pidx*3+1] - xb[s*3+1];
            float dz = xb[pidx*3+2] - xb[s*3+2];
            const float* f1p = g_F1 + ((size_t)b * N_ + pidx) * 64 + j0;
#pragma unroll
            for (int jj = 0; jj < 16; jj += 4) {
                float4 f = *(const float4*)(f1p + jj);
                int j = j0 + jj;
                float v0 = f.x + dx*sW1x[j+0] + dy*sW1x[64+j+0] + dz*sW1x[128+j+0];
                float v1 = f.y + dx*sW1x[j+1] + dy*sW1x[64+j+1] + dz*sW1x[128+j+1];
                float v2 = f.z + dx*sW1x[j+2] + dy*sW1x[64+j+2] + dz*sW1x[128+j+2];
                float v3 = f.w + dx*sW1x[j+3] + dy*sW1x[64+j+3] + dz*sW1x[128+j+3];
                h1T[(j+0)*32 + n] = fmaxf(v0, 0.f);
                h1T[(j+1)*32 + n] = fmaxf(v1, 0.f);
                h1T[(j+2)*32 + n] = fmaxf(v2, 0.f);
                h1T[(j+3)*32 + n] = fmaxf(v3, 0.f);
            }
        }
        __syncthreads();

        // ---- layer 2: h2[n][c] = relu(b2 + sum_k h1[n][k] W2[k][c]) ----
        {
            float acc[4][4];
#pragma unroll
            for (int j = 0; j < 4; j++) {
                float bv = sb2[c2 + j];
                acc[0][j]=bv; acc[1][j]=bv; acc[2][j]=bv; acc[3][j]=bv;
            }
#pragma unroll 8
            for (int k = 0; k < 64; k++) {
                float4 a = *(const float4*)(h1T + k*32 + n0);
                float4 w = *(const float4*)(sW2 + k*64 + c2);
                acc[0][0] += a.x*w.x; acc[0][1] += a.x*w.y; acc[0][2] += a.x*w.z; acc[0][3] += a.x*w.w;
                acc[1][0] += a.y*w.x; acc[1][1] += a.y*w.y; acc[1][2] += a.y*w.z; acc[1][3] += a.y*w.w;
                acc[2][0] += a.z*w.x; acc[2][1] += a.z*w.y; acc[2][2] += a.z*w.z; acc[2][3] += a.z*w.w;
                acc[3][0] += a.w*w.x; acc[3][1] += a.w*w.y; acc[3][2] += a.w*w.z; acc[3][3] += a.w*w.w;
            }
#pragma unroll
            for (int j = 0; j < 4; j++) {
                float4 v = make_float4(fmaxf(acc[0][j],0.f), fmaxf(acc[1][j],0.f),
                                       fmaxf(acc[2][j],0.f), fmaxf(acc[3][j],0.f));
                *(float4*)(h2T + (c2+j)*32 + n0) = v;
            }
        }
        __syncthreads();

        // ---- layer 3 + relu + max over neighbors ----
        {
            float acc[4][8];
#pragma unroll
            for (int j = 0; j < 8; j++) {
                float bv = sb3[c3 + j];
                acc[0][j]=bv; acc[1][j]=bv; acc[2][j]=bv; acc[3][j]=bv;
            }
#pragma unroll 8
            for (int k = 0; k < 64; k++) {
                float4 a  = *(const float4*)(h2T + k*32 + n0);
                float4 w0 = *(const float4*)(sW3 + k*128 + c3);
                float4 w1 = *(const float4*)(sW3 + k*128 + c3 + 4);
                acc[0][0]+=a.x*w0.x; acc[0][1]+=a.x*w0.y; acc[0][2]+=a.x*w0.z; acc[0][3]+=a.x*w0.w;
                acc[0][4]+=a.x*w1.x; acc[0][5]+=a.x*w1.y; acc[0][6]+=a.x*w1.z; acc[0][7]+=a.x*w1.w;
                acc[1][0]+=a.y*w0.x; acc[1][1]+=a.y*w0.y; acc[1][2]+=a.y*w0.z; acc[1][3]+=a.y*w0.w;
                acc[1][4]+=a.y*w1.x; acc[1][5]+=a.y*w1.y; acc[1][6]+=a.y*w1.z; acc[1][7]+=a.y*w1.w;
                acc[2][0]+=a.z*w0.x; acc[2][1]+=a.z*w0.y; acc[2][2]+=a.z*w0.z; acc[2][3]+=a.z*w0.w;
                acc[2][4]+=a.z*w1.x; acc[2][5]+=a.z*w1.y; acc[2][6]+=a.z*w1.z; acc[2][7]+=a.z*w1.w;
                acc[3][0]+=a.w*w0.x; acc[3][1]+=a.w*w0.y; acc[3][2]+=a.w*w0.z; acc[3][3]+=a.w*w0.w;
                acc[3][4]+=a.w*w1.x; acc[3][5]+=a.w*w1.y; acc[3][6]+=a.w*w1.z; acc[3][7]+=a.w*w1.w;
            }
            float m[8];
#pragma unroll
            for (int j = 0; j < 8; j++)
                m[j] = fmaxf(fmaxf(fmaxf(acc[0][j], acc[1][j]),
                                   fmaxf(acc[2][j], acc[3][j])), 0.f);
#pragma unroll
            for (int off = 1; off < 8; off <<= 1) {
#pragma unroll
                for (int j = 0; j < 8; j++)
                    m[j] = fmaxf(m[j], __shfl_xor_sync(0xffffffffu, m[j], off));
            }
            if (tr == 0) {
                float* o = outf + ((size_t)b * 128 + c3) * S_ + s;
#pragma unroll
                for (int j = 0; j < 8; j++) o[(size_t)j * S_] = m[j];
            }
        }
        __syncthreads();
    }
}

// ---------------------------------------------------------------------------
// Kernel 4: new_xyz copy + samp_idx (as float values)
// ---------------------------------------------------------------------------
__global__ void k_out(const float* __restrict__ xyz, float* __restrict__ out) {
    int i = blockIdx.x * blockDim.x + threadIdx.x;
    if (i < B_ * S_ * 3) {
        int b = i / (S_ * 3), r = i % (S_ * 3);
        out[i] = xyz[(size_t)b * N_ * 3 + r];
    } else {
        int j = i - B_ * S_ * 3;
        if (j < B_ * S_)
            out[B_*S_*3 + (size_t)B_*128*S_ + j] = (float)(j & (S_ - 1));
    }
}

// ---------------------------------------------------------------------------
extern "C" void kernel_launch(void* const* d_in, const int* in_sizes, int n_in,
                              void* d_out, int out_size) {
    const float* xyz   = (const float*)d_in[0];
    const float* feats = (const float*)d_in[1];
    const float* W1    = (const float*)d_in[2];
    const float* b1    = (const float*)d_in[3];
    const float* W2    = (const float*)d_in[4];
    const float* b2    = (const float*)d_in[5];
    const float* W3    = (const float*)d_in[6];
    const float* b3    = (const float*)d_in[7];
    float* out = (float*)d_out;

    const int NXYZ = B_ * S_ * 3;               // 24576
    const int NFEA = B_ * 128 * S_;             // 1048576
    float* outf = out + NXYZ;                   // features region (full tuple layout)
    bool full_layout = (out_size >= NXYZ + NFEA + B_ * S_);
    if (!full_layout && out_size == NFEA) outf = out;  // features-only fallback

    const size_t smem_mlp = 16768 * sizeof(float);  // 67072 B
    cudaFuncSetAttribute(k_mlp, cudaFuncAttributeMaxDynamicSharedMemorySize,
                         (int)smem_mlp);

    k_f1<<<dim3(N_/64, B_), 256>>>(feats, W1, b1);
    k_bq<<<NCID/8, 256>>>(xyz);
    k_mlp<<<NCID/8, 128, smem_mlp>>>(xyz, W1, W2, b2, W3, b3, outf);
    if (full_layout) {
        int tot = NXYZ + B_ * S_;
        k_out<<<(tot + 255)/256, 256>>>(xyz, out);
    }
}